// round 2
// baseline (speedup 1.0000x reference)
#include <cuda_runtime.h>
#include <cstdint>

#define N_NODES 50000
#define NNZ_C   800000
#define N_ADJ   6
#define K_DIM   256
#define H_DIM   128
#define LN_EPS  1e-5f

// ---------------------------------------------------------------------------
// Device-global scratch (no allocations allowed)
// ---------------------------------------------------------------------------
__device__ float g_h[(size_t)N_NODES * H_DIM];              // s0 = x@W+b
__device__ float g_state[3][(size_t)N_NODES * H_DIM];       // s1, s2, s3
__device__ int   g_wcur[N_ADJ][N_NODES];                    // counts, then cursors
__device__ int   g_rowptr[N_ADJ][N_NODES + 1];              // CSR row pointers
__device__ int2  g_edges[N_ADJ][NNZ_C];                     // packed (col, val bits)

__device__ __forceinline__ float* state_ptr(int id) {
    return (id == 0) ? g_h : g_state[id - 1];
}

// ---------------------------------------------------------------------------
// CSR build: zero counters -> histogram -> scan -> scatter
// ---------------------------------------------------------------------------
__global__ void zero_cnt_kernel() {
    const int n = N_ADJ * N_NODES;
    int* p = &g_wcur[0][0];
    for (int i = blockIdx.x * blockDim.x + threadIdx.x; i < n;
         i += gridDim.x * blockDim.x)
        p[i] = 0;
}

__global__ __launch_bounds__(256) void hist_kernel(const int* __restrict__ rows_base) {
    const int n = N_ADJ * NNZ_C;
    for (int i = blockIdx.x * blockDim.x + threadIdx.x; i < n;
         i += gridDim.x * blockDim.x) {
        const int a = i / NNZ_C;
        const int row = __ldg(rows_base + i);
        atomicAdd(&g_wcur[a][row], 1);
    }
}

// One block per adjacency. 256 threads, each owns a contiguous chunk of rows.
__global__ __launch_bounds__(256) void scan_kernel() {
    const int a = blockIdx.x;
    const int t = threadIdx.x;
    const int CHUNK = (N_NODES + 255) / 256;   // 196
    const int start = t * CHUNK;
    const int end = min(start + CHUNK, N_NODES);

    int sum = 0;
    for (int r = start; r < end; r++) sum += g_wcur[a][r];

    __shared__ int sh[256];
    sh[t] = sum;
    __syncthreads();
    // Hillis-Steele inclusive scan
    for (int off = 1; off < 256; off <<= 1) {
        int v = (t >= off) ? sh[t - off] : 0;
        __syncthreads();
        sh[t] += v;
        __syncthreads();
    }
    int run = sh[t] - sum;   // exclusive prefix
    for (int r = start; r < end; r++) {
        const int c = g_wcur[a][r];
        g_rowptr[a][r] = run;
        g_wcur[a][r] = run;   // becomes scatter cursor
        run += c;
    }
    if (t == 255) g_rowptr[a][N_NODES] = run;
}

__global__ __launch_bounds__(256) void scatter_kernel(const int*   __restrict__ rows_base,
                                                      const int*   __restrict__ cols_base,
                                                      const float* __restrict__ vals_base) {
    const int n = N_ADJ * NNZ_C;
    for (int i = blockIdx.x * blockDim.x + threadIdx.x; i < n;
         i += gridDim.x * blockDim.x) {
        const int a   = i / NNZ_C;
        const int row = __ldg(rows_base + i);
        const int col = __ldg(cols_base + i);
        const float v = __ldg(vals_base + i);
        const int pos = atomicAdd(&g_wcur[a][row], 1);
        g_edges[a][pos] = make_int2(col, __float_as_int(v));
    }
}

// ---------------------------------------------------------------------------
// GEMM: g_h = X[50000,256] @ W[256,128] + b   (128x128 tile, 8x8/thread)
// ---------------------------------------------------------------------------
__global__ __launch_bounds__(256) void gemm_kernel(const float* __restrict__ X,
                                                   const float* __restrict__ W,
                                                   const float* __restrict__ bias) {
    __shared__ float As[8][128];
    __shared__ float Bs[8][128];

    const int tid = threadIdx.x;
    const int tx = tid & 15;
    const int ty = tid >> 4;
    const int row0 = blockIdx.x * 128;

    const int arow = tid >> 1;
    const int ak   = (tid & 1) * 4;
    const int grow = min(row0 + arow, N_NODES - 1);
    const int brow = tid >> 5;
    const int bcol = (tid & 31) * 4;

    float acc[8][8];
#pragma unroll
    for (int i = 0; i < 8; i++)
#pragma unroll
        for (int j = 0; j < 8; j++) acc[i][j] = 0.f;

    for (int k0 = 0; k0 < K_DIM; k0 += 8) {
        const float4 av = *reinterpret_cast<const float4*>(
            X + (size_t)grow * K_DIM + k0 + ak);
        const float4 bv = *reinterpret_cast<const float4*>(
            W + (size_t)(k0 + brow) * H_DIM + bcol);
        __syncthreads();
        As[ak + 0][arow] = av.x;
        As[ak + 1][arow] = av.y;
        As[ak + 2][arow] = av.z;
        As[ak + 3][arow] = av.w;
        *reinterpret_cast<float4*>(&Bs[brow][bcol]) = bv;
        __syncthreads();

#pragma unroll
        for (int kk = 0; kk < 8; kk++) {
            float a[8], b[8];
            const float4 a0 = *reinterpret_cast<const float4*>(&As[kk][ty * 8]);
            const float4 a1 = *reinterpret_cast<const float4*>(&As[kk][ty * 8 + 4]);
            const float4 b0 = *reinterpret_cast<const float4*>(&Bs[kk][tx * 8]);
            const float4 b1 = *reinterpret_cast<const float4*>(&Bs[kk][tx * 8 + 4]);
            a[0]=a0.x; a[1]=a0.y; a[2]=a0.z; a[3]=a0.w;
            a[4]=a1.x; a[5]=a1.y; a[6]=a1.z; a[7]=a1.w;
            b[0]=b0.x; b[1]=b0.y; b[2]=b0.z; b[3]=b0.w;
            b[4]=b1.x; b[5]=b1.y; b[6]=b1.z; b[7]=b1.w;
#pragma unroll
            for (int i = 0; i < 8; i++)
#pragma unroll
                for (int j = 0; j < 8; j++) acc[i][j] += a[i] * b[j];
        }
    }

    const int colb = tx * 8;
    const float4 bia0 = *reinterpret_cast<const float4*>(bias + colb);
    const float4 bia1 = *reinterpret_cast<const float4*>(bias + colb + 4);
#pragma unroll
    for (int i = 0; i < 8; i++) {
        const int row = row0 + ty * 8 + i;
        if (row < N_NODES) {
            float4 o0, o1;
            o0.x = acc[i][0] + bia0.x; o0.y = acc[i][1] + bia0.y;
            o0.z = acc[i][2] + bia0.z; o0.w = acc[i][3] + bia0.w;
            o1.x = acc[i][4] + bia1.x; o1.y = acc[i][5] + bia1.y;
            o1.z = acc[i][6] + bia1.z; o1.w = acc[i][7] + bia1.w;
            float* op = g_h + (size_t)row * H_DIM + colb;
            *reinterpret_cast<float4*>(op)     = o0;
            *reinterpret_cast<float4*>(op + 4) = o1;
        }
    }
}

// ---------------------------------------------------------------------------
// CSR SpMM step: one warp per destination row. Accumulates up to 3 adjacency
// terms (each with its own source state) in registers, stores once. No atomics.
// ---------------------------------------------------------------------------
__global__ __launch_bounds__(256) void spmm_step_kernel(const int* __restrict__ ip0, int s0,
                                                        const int* __restrict__ ip1, int s1,
                                                        const int* __restrict__ ip2, int s2,
                                                        int nterms, int dst_id) {
    const int lane = threadIdx.x & 31;
    const int row  = (blockIdx.x * blockDim.x + threadIdx.x) >> 5;
    if (row >= N_NODES) return;

    float4 acc = make_float4(0.f, 0.f, 0.f, 0.f);

#pragma unroll 1
    for (int t = 0; t < nterms; t++) {
        const int* ip  = (t == 0) ? ip0 : (t == 1) ? ip1 : ip2;
        const int  sid = (t == 0) ? s0  : (t == 1) ? s1  : s2;
        const int  a   = __ldg(ip);
        const float* __restrict__ src = state_ptr(sid);
        const int2* __restrict__ el = g_edges[a];
        const int beg = __ldg(&g_rowptr[a][row]);
        const int end = __ldg(&g_rowptr[a][row + 1]);
        for (int e = beg; e < end; e++) {
            const int2 cv = __ldg(&el[e]);
            const float v = __int_as_float(cv.y);
            const float4 xv = __ldg(reinterpret_cast<const float4*>(
                                        src + (size_t)cv.x * H_DIM) + lane);
            acc.x += v * xv.x;
            acc.y += v * xv.y;
            acc.z += v * xv.z;
            acc.w += v * xv.w;
        }
    }

    float* dst = state_ptr(dst_id);
    *reinterpret_cast<float4*>(dst + (size_t)row * H_DIM + lane * 4) = acc;
}

// ---------------------------------------------------------------------------
// LayerNorm + exact-erf GELU, one warp per row
// ---------------------------------------------------------------------------
__global__ __launch_bounds__(256) void ln_gelu_kernel(const float* __restrict__ gamma,
                                                      const float* __restrict__ beta,
                                                      float* __restrict__ out) {
    const int warp = (blockIdx.x * blockDim.x + threadIdx.x) >> 5;
    const int lane = threadIdx.x & 31;
    if (warp >= N_NODES) return;

    const float* yrow = g_state[2] + (size_t)warp * H_DIM;
    const float4 v = *reinterpret_cast<const float4*>(yrow + lane * 4);

    float s  = v.x + v.y + v.z + v.w;
    float sq = v.x * v.x + v.y * v.y + v.z * v.z + v.w * v.w;
#pragma unroll
    for (int o = 16; o; o >>= 1) {
        s  += __shfl_xor_sync(0xFFFFFFFFu, s,  o);
        sq += __shfl_xor_sync(0xFFFFFFFFu, sq, o);
    }
    const float mean = s * (1.f / H_DIM);
    const float var  = sq * (1.f / H_DIM) - mean * mean;
    const float rstd = rsqrtf(var + LN_EPS);

    const float4 g = *reinterpret_cast<const float4*>(gamma + lane * 4);
    const float4 b = *reinterpret_cast<const float4*>(beta  + lane * 4);

    auto gelu = [](float t) {
        return 0.5f * t * (1.f + erff(t * 0.7071067811865476f));
    };
    float4 r;
    r.x = gelu((v.x - mean) * rstd * g.x + b.x);
    r.y = gelu((v.y - mean) * rstd * g.y + b.y);
    r.z = gelu((v.z - mean) * rstd * g.z + b.z);
    r.w = gelu((v.w - mean) * rstd * g.w + b.w);

    *reinterpret_cast<float4*>(out + (size_t)warp * H_DIM + lane * 4) = r;
}

// ---------------------------------------------------------------------------
// kernel_launch
// inputs: x, adj_rows, adj_cols, adj_vals, idxes_seq, idxes_res,
//         W, b, gamma, beta
// ---------------------------------------------------------------------------
extern "C" void kernel_launch(void* const* d_in, const int* in_sizes, int n_in,
                              void* d_out, int out_size) {
    const float* x        = (const float*)d_in[0];
    const int*   adj_rows = (const int*)  d_in[1];
    const int*   adj_cols = (const int*)  d_in[2];
    const float* adj_vals = (const float*)d_in[3];
    const int*   idx_seq  = (const int*)  d_in[4];
    const int*   idx_res  = (const int*)  d_in[5];
    const float* W        = (const float*)d_in[6];
    const float* b        = (const float*)d_in[7];
    const float* gamma    = (const float*)d_in[8];
    const float* beta     = (const float*)d_in[9];
    float*       out      = (float*)d_out;

    // ---- CSR build (device-side; selectors are device-resident) ----
    zero_cnt_kernel<<<512, 256>>>();
    hist_kernel<<<2048, 256>>>(adj_rows);
    scan_kernel<<<N_ADJ, 256>>>();
    scatter_kernel<<<2048, 256>>>(adj_rows, adj_cols, adj_vals);

    // ---- affine ----
    gemm_kernel<<<(N_NODES + 127) / 128, 256>>>(x, W, b);

    // ---- propagation steps (state ids: 0=s0, 1=s1, 2=s2, 3=s3) ----
    const int SPMM_GRID = (N_NODES * 32 + 255) / 256;   // one warp per row
    // s1 = A[seq0] @ s0
    spmm_step_kernel<<<SPMM_GRID, 256>>>(idx_seq + 0, 0,
                                         idx_seq + 0, 0,
                                         idx_seq + 0, 0, 1, 1);
    // s2 = A[seq1] @ s1 + A[res0] @ s0
    spmm_step_kernel<<<SPMM_GRID, 256>>>(idx_seq + 1, 1,
                                         idx_res + 0, 0,
                                         idx_res + 0, 0, 2, 2);
    // s3 = A[seq2] @ s2 + A[res1] @ s0 + A[res2] @ s1
    spmm_step_kernel<<<SPMM_GRID, 256>>>(idx_seq + 2, 2,
                                         idx_res + 1, 0,
                                         idx_res + 2, 1, 3, 3);

    // ---- LN + GELU ----
    ln_gelu_kernel<<<(N_NODES * 32 + 255) / 256, 256>>>(gamma, beta, out);
}